// round 1
// baseline (speedup 1.0000x reference)
#include <cuda_runtime.h>
#include <math.h>

#define NNODES 50000
#define NEDGES 800000
#define F_INV  128
#define HC1    256   // HEADS*HID for layers 1,2
#define HC3    64    // layer 3 (1 head, 64 ch)

// ---------------- scratch (static device globals; no runtime allocation) ----
__device__ float g_xl [(size_t)NNODES * HC1];
__device__ float g_xr [(size_t)NNODES * HC1];
__device__ float g_h  [(size_t)NNODES * HC1];
__device__ float g_agg[(size_t)NNODES * HC1];
__device__ float g_p  [(size_t)NEDGES * 4];
__device__ float g_m  [(size_t)NNODES * 4];
__device__ float g_den[(size_t)NNODES * 4];

// ---------------- helpers ---------------------------------------------------
__device__ __forceinline__ void atomicMaxFloat(float* addr, float val) {
    int* ia = (int*)addr;
    int old = *ia;
    while (__int_as_float(old) < val) {
        int assumed = old;
        old = atomicCAS(ia, assumed, __float_as_int(val));
        if (old == assumed) break;
    }
}

__global__ void fill_kernel(float* __restrict__ p, float v, int n) {
    int i = blockIdx.x * blockDim.x + threadIdx.x;
    if (i < n) p[i] = v;
}

// ---------------- SGEMM: C[M,Nc] = A[M,K] @ B[K,Nc] (+bias) -----------------
// 64x64 tile, BK=16, 256 threads, 4x4 per thread. K%16==0, Nc%64==0 required.
__global__ __launch_bounds__(256) void sgemm_bias(
    const float* __restrict__ A, const float* __restrict__ B,
    const float* __restrict__ bias, float* __restrict__ C,
    int M, int K, int Nc)
{
    __shared__ float As[16][64];
    __shared__ float Bs[16][64];
    const int tid = threadIdx.x;
    const int tx = tid & 15, ty = tid >> 4;
    const int row0 = blockIdx.y * 64;
    const int col0 = blockIdx.x * 64;

    float acc[4][4];
#pragma unroll
    for (int i = 0; i < 4; i++)
#pragma unroll
        for (int j = 0; j < 4; j++) acc[i][j] = 0.f;

    const int ar = tid >> 2;          // 0..63  (A tile row)
    const int ac = (tid & 3) * 4;     // 0..12  (A tile col, float4)
    const int br = tid >> 4;          // 0..15  (B tile row)
    const int bc = (tid & 15) * 4;    // 0..60  (B tile col, float4)

    for (int k0 = 0; k0 < K; k0 += 16) {
        float4 av;
        if (row0 + ar < M) av = *(const float4*)(A + (size_t)(row0 + ar) * K + k0 + ac);
        else               av = make_float4(0.f, 0.f, 0.f, 0.f);
        As[ac + 0][ar] = av.x; As[ac + 1][ar] = av.y;
        As[ac + 2][ar] = av.z; As[ac + 3][ar] = av.w;

        float4 bv = *(const float4*)(B + (size_t)(k0 + br) * Nc + col0 + bc);
        Bs[br][bc + 0] = bv.x; Bs[br][bc + 1] = bv.y;
        Bs[br][bc + 2] = bv.z; Bs[br][bc + 3] = bv.w;
        __syncthreads();

#pragma unroll
        for (int k = 0; k < 16; k++) {
            float a[4], b[4];
#pragma unroll
            for (int i = 0; i < 4; i++) a[i] = As[k][ty * 4 + i];
#pragma unroll
            for (int j = 0; j < 4; j++) b[j] = Bs[k][tx * 4 + j];
#pragma unroll
            for (int i = 0; i < 4; i++)
#pragma unroll
                for (int j = 0; j < 4; j++) acc[i][j] += a[i] * b[j];
        }
        __syncthreads();
    }

#pragma unroll
    for (int i = 0; i < 4; i++) {
        int rr = row0 + ty * 4 + i;
        if (rr >= M) continue;
#pragma unroll
        for (int j = 0; j < 4; j++) {
            int cc = col0 + tx * 4 + j;
            float v = acc[i][j];
            if (bias) v += bias[cc];
            C[(size_t)rr * Nc + cc] = v;
        }
    }
}

// ---------------- edge pass A: per-edge attention logits + segment max ------
// one warp per edge; lane covers HC/32 contiguous channels.
template <int H, int C>
__global__ __launch_bounds__(256) void edge_score(
    const float* __restrict__ xl, const float* __restrict__ xr,
    const int* __restrict__ src, const int* __restrict__ dst,
    const float* __restrict__ att, float* __restrict__ score,
    float* __restrict__ m, int E)
{
    constexpr int HCv = H * C;
    constexpr int PL  = HCv / 32;
    constexpr int LPH = 32 / H;     // lanes per head
    int e = blockIdx.x * 8 + (threadIdx.x >> 5);
    if (e >= E) return;
    int lane = threadIdx.x & 31;
    int s = src[e], d = dst[e];

    const float* pl = xl + (size_t)s * HCv + lane * PL;
    const float* pr = xr + (size_t)d * HCv + lane * PL;
    const float* pa = att + lane * PL;

    float acc = 0.f;
    if constexpr (PL >= 4) {
#pragma unroll
        for (int i = 0; i < PL; i += 4) {
            float4 a = *(const float4*)(pl + i);
            float4 b = *(const float4*)(pr + i);
            float4 w = *(const float4*)(pa + i);
            float v;
            v = a.x + b.x; v = v > 0.f ? v : 0.2f * v; acc += w.x * v;
            v = a.y + b.y; v = v > 0.f ? v : 0.2f * v; acc += w.y * v;
            v = a.z + b.z; v = v > 0.f ? v : 0.2f * v; acc += w.z * v;
            v = a.w + b.w; v = v > 0.f ? v : 0.2f * v; acc += w.w * v;
        }
    } else {
        float2 a = *(const float2*)pl;
        float2 b = *(const float2*)pr;
        float2 w = *(const float2*)pa;
        float v;
        v = a.x + b.x; v = v > 0.f ? v : 0.2f * v; acc += w.x * v;
        v = a.y + b.y; v = v > 0.f ? v : 0.2f * v; acc += w.y * v;
    }

#pragma unroll
    for (int o = LPH / 2; o > 0; o >>= 1)
        acc += __shfl_xor_sync(0xffffffffu, acc, o);

    if ((lane & (LPH - 1)) == 0) {
        int h = lane / LPH;
        score[(size_t)e * H + h] = acc;
        atomicMaxFloat(m + (size_t)d * H + h, acc);
    }
}

// ---------------- edge pass B: p = exp(score - m[dst]); segment sum ---------
__global__ void edge_exp(
    float* __restrict__ sc, const float* __restrict__ m,
    float* __restrict__ den, const int* __restrict__ dst, int E, int H)
{
    int i = blockIdx.x * blockDim.x + threadIdx.x;
    if (i >= E * H) return;
    int e = i / H, h = i - e * H;
    int d = dst[e];
    float pv = expf(sc[i] - m[d * H + h]);
    sc[i] = pv;
    atomicAdd(den + (size_t)d * H + h, pv);
}

// ---------------- edge pass C: out[dst] += alpha * xl[src] ------------------
template <int H, int C>
__global__ __launch_bounds__(256) void edge_agg(
    const float* __restrict__ xl,
    const int* __restrict__ src, const int* __restrict__ dst,
    const float* __restrict__ p, const float* __restrict__ den,
    float* __restrict__ agg, int E)
{
    constexpr int HCv = H * C;
    constexpr int PL  = HCv / 32;
    constexpr int LPH = 32 / H;
    int e = blockIdx.x * 8 + (threadIdx.x >> 5);
    if (e >= E) return;
    int lane = threadIdx.x & 31;
    int s = src[e], d = dst[e];
    int h = lane / LPH;
    float alpha = p[(size_t)e * H + h] / (den[(size_t)d * H + h] + 1e-16f);

    const float* pl = xl + (size_t)s * HCv + lane * PL;
    float* po = agg + (size_t)d * HCv + lane * PL;
#pragma unroll
    for (int i = 0; i < PL; i++)
        atomicAdd(po + i, alpha * pl[i]);
}

// ---------------- finalize: out = [elu](agg + bias) -------------------------
__global__ void finalize_kernel(
    const float* __restrict__ agg, const float* __restrict__ bias,
    float* __restrict__ out, int total, int HCv, int doElu)
{
    int i = blockIdx.x * blockDim.x + threadIdx.x;
    if (i >= total) return;
    float v = agg[i] + bias[i % HCv];
    out[i] = doElu ? (v > 0.f ? v : expm1f(v)) : v;
}

// ---------------- host driver ------------------------------------------------
static void run_layer(const float* in, int K,
                      const float* Wl, const float* Wr,
                      const float* att, const float* bias,
                      int H, int C,
                      const int* src, const int* dst,
                      float* xl, float* xr, float* agg, float* p,
                      float* m, float* den,
                      float* out, bool elu)
{
    int HCv = H * C;
    dim3 gg((HCv + 63) / 64, (NNODES + 63) / 64);
    sgemm_bias<<<gg, 256>>>(in, Wl, nullptr, xl, NNODES, K, HCv);
    sgemm_bias<<<gg, 256>>>(in, Wr, nullptr, xr, NNODES, K, HCv);

    int nmh = NNODES * H;
    fill_kernel<<<(nmh + 255) / 256, 256>>>(m, -3.0e38f, nmh);
    cudaMemsetAsync(den, 0, (size_t)nmh * sizeof(float), 0);
    cudaMemsetAsync(agg, 0, (size_t)NNODES * HCv * sizeof(float), 0);

    int eb = (NEDGES + 7) / 8;
    if (H == 4) edge_score<4, 64><<<eb, 256>>>(xl, xr, src, dst, att, p, m, NEDGES);
    else        edge_score<1, 64><<<eb, 256>>>(xl, xr, src, dst, att, p, m, NEDGES);

    int eh = NEDGES * H;
    edge_exp<<<(eh + 255) / 256, 256>>>(p, m, den, dst, NEDGES, H);

    if (H == 4) edge_agg<4, 64><<<eb, 256>>>(xl, src, dst, p, den, agg, NEDGES);
    else        edge_agg<1, 64><<<eb, 256>>>(xl, src, dst, p, den, agg, NEDGES);

    int tot = NNODES * HCv;
    finalize_kernel<<<(tot + 255) / 256, 256>>>(agg, bias, out, tot, HCv, elu ? 1 : 0);
}

extern "C" void kernel_launch(void* const* d_in, const int* in_sizes, int n_in,
                              void* d_out, int out_size)
{
    const float* x    = (const float*)d_in[0];
    const float* Wl1  = (const float*)d_in[1];
    const float* Wr1  = (const float*)d_in[2];
    const float* att1 = (const float*)d_in[3];
    const float* b1   = (const float*)d_in[4];
    const float* Wl2  = (const float*)d_in[5];
    const float* Wr2  = (const float*)d_in[6];
    const float* att2 = (const float*)d_in[7];
    const float* b2   = (const float*)d_in[8];
    const float* Wl3  = (const float*)d_in[9];
    const float* Wr3  = (const float*)d_in[10];
    const float* att3 = (const float*)d_in[11];
    const float* b3   = (const float*)d_in[12];
    const float* Wlin = (const float*)d_in[13];
    const float* blin = (const float*)d_in[14];
    const int*   ei   = (const int*)d_in[15];

    const int* src = ei;
    const int* dst = ei + NEDGES;

    void* tp;
    float *xl, *xr, *h, *agg, *p, *m, *den;
    cudaGetSymbolAddress(&tp, g_xl);  xl  = (float*)tp;
    cudaGetSymbolAddress(&tp, g_xr);  xr  = (float*)tp;
    cudaGetSymbolAddress(&tp, g_h);   h   = (float*)tp;
    cudaGetSymbolAddress(&tp, g_agg); agg = (float*)tp;
    cudaGetSymbolAddress(&tp, g_p);   p   = (float*)tp;
    cudaGetSymbolAddress(&tp, g_m);   m   = (float*)tp;
    cudaGetSymbolAddress(&tp, g_den); den = (float*)tp;

    // Layer 1: 128 -> 4x64, ELU
    run_layer(x, F_INV, Wl1, Wr1, att1, b1, 4, 64, src, dst,
              xl, xr, agg, p, m, den, h, true);
    // Layer 2: 256 -> 4x64, ELU
    run_layer(h, HC1, Wl2, Wr2, att2, b2, 4, 64, src, dst,
              xl, xr, agg, p, m, den, h, true);
    // Layer 3: 256 -> 1x64, no activation
    run_layer(h, HC1, Wl3, Wr3, att3, b3, 1, 64, src, dst,
              xl, xr, agg, p, m, den, h, false);

    // Final linear: out = h @ Wlin + blin  (50000x64 @ 64x64)
    dim3 gf(1, (NNODES + 63) / 64);
    sgemm_bias<<<gf, 256>>>(h, Wlin, blin, (float*)d_out, NNODES, HC3, HC3);
}

// round 2
// speedup vs baseline: 3.2687x; 3.2687x over previous
#include <cuda_runtime.h>
#include <math.h>

#define NNODES 50000
#define NEDGES 800000

// ---------------- scratch (static device globals; no runtime allocation) ----
__device__ float g_xlr[(size_t)NNODES * 512];   // fused [xl | xr], stride 2*HC
__device__ float g_h  [(size_t)NNODES * 256];   // layer activations
__device__ float g_W  [256 * 512];              // packed fused weights
__device__ int   g_deg [NNODES + 1];
__device__ int   g_rowp[NNODES + 1];
__device__ int   g_pos [NNODES];
__device__ int   g_csrc[NEDGES];

// ======================= CSR build ==========================================
__global__ void hist_kernel(const int* __restrict__ dst, int* __restrict__ deg, int E) {
    int i = blockIdx.x * blockDim.x + threadIdx.x;
    if (i < E) atomicAdd(&deg[dst[i]], 1);
}

__global__ void scan_kernel(const int* __restrict__ deg, int* __restrict__ rowp,
                            int* __restrict__ pos, int n, int E) {
    __shared__ int sums[1024];
    const int tid = threadIdx.x;
    const int CH = (n + 1023) / 1024;
    const int start = tid * CH;
    int local = 0;
    for (int i = 0; i < CH; i++) {
        int idx = start + i;
        if (idx < n) local += deg[idx];
    }
    sums[tid] = local;
    __syncthreads();
    for (int off = 1; off < 1024; off <<= 1) {
        int v = (tid >= off) ? sums[tid - off] : 0;
        __syncthreads();
        sums[tid] += v;
        __syncthreads();
    }
    int prefix = (tid == 0) ? 0 : sums[tid - 1];
    for (int i = 0; i < CH; i++) {
        int idx = start + i;
        if (idx < n) {
            rowp[idx] = prefix;
            pos[idx]  = prefix;
            prefix += deg[idx];
        }
    }
    if (tid == 1023) rowp[n] = E;
}

__global__ void fillcsr_kernel(const int* __restrict__ src, const int* __restrict__ dst,
                               int* __restrict__ pos, int* __restrict__ csrc, int E) {
    int i = blockIdx.x * blockDim.x + threadIdx.x;
    if (i < E) {
        int p = atomicAdd(&pos[dst[i]], 1);
        csrc[p] = src[i];
    }
}

// ======================= weight pack: W = [Wl | Wr] =========================
__global__ void pack2_kernel(const float* __restrict__ Wl, const float* __restrict__ Wr,
                             float* __restrict__ W, int K, int HC) {
    int i = blockIdx.x * blockDim.x + threadIdx.x;
    int tot = K * HC;
    if (i >= tot) return;
    int k = i / HC, c = i - k * HC;
    W[(size_t)k * 2 * HC + c]      = Wl[i];
    W[(size_t)k * 2 * HC + HC + c] = Wr[i];
}

// ======================= SGEMM 128x128, BK=8, 8x8/thread ===================
// C[M,Nc] = A[M,K] @ B[K,Nc]. Requires K%8==0, Nc%128==0. M-edge guarded.
__global__ __launch_bounds__(256) void sgemm128(
    const float* __restrict__ A, const float* __restrict__ B,
    float* __restrict__ C, int M, int K, int Nc)
{
    __shared__ float As[2][8][128];
    __shared__ float Bs[2][8][128];
    const int tid = threadIdx.x;
    const int row0 = blockIdx.y * 128;
    const int col0 = blockIdx.x * 128;
    const int tx = tid & 15, ty = tid >> 4;

    const int ar = tid >> 1, ac = (tid & 1) * 4;   // A: 128 rows x 8 cols
    const int br = tid >> 5, bc = (tid & 31) * 4;  // B: 8 rows x 128 cols

    float acc[8][8];
#pragma unroll
    for (int i = 0; i < 8; i++)
#pragma unroll
        for (int j = 0; j < 8; j++) acc[i][j] = 0.f;

    // preload first tile
    float4 av, bv;
    if (row0 + ar < M) av = *(const float4*)(A + (size_t)(row0 + ar) * K + ac);
    else               av = make_float4(0.f, 0.f, 0.f, 0.f);
    bv = *(const float4*)(B + (size_t)br * Nc + col0 + bc);

    As[0][ac + 0][ar] = av.x; As[0][ac + 1][ar] = av.y;
    As[0][ac + 2][ar] = av.z; As[0][ac + 3][ar] = av.w;
    Bs[0][br][bc + 0] = bv.x; Bs[0][br][bc + 1] = bv.y;
    Bs[0][br][bc + 2] = bv.z; Bs[0][br][bc + 3] = bv.w;
    __syncthreads();

    int buf = 0;
    for (int k0 = 0; k0 < K; k0 += 8) {
        bool more = (k0 + 8) < K;
        if (more) {
            if (row0 + ar < M) av = *(const float4*)(A + (size_t)(row0 + ar) * K + k0 + 8 + ac);
            else               av = make_float4(0.f, 0.f, 0.f, 0.f);
            bv = *(const float4*)(B + (size_t)(k0 + 8 + br) * Nc + col0 + bc);
        }
#pragma unroll
        for (int k = 0; k < 8; k++) {
            float a[8], b[8];
#pragma unroll
            for (int i = 0; i < 4; i++) {
                a[i]     = As[buf][k][ty * 4 + i];
                a[i + 4] = As[buf][k][ty * 4 + i + 64];
                b[i]     = Bs[buf][k][tx * 4 + i];
                b[i + 4] = Bs[buf][k][tx * 4 + i + 64];
            }
#pragma unroll
            for (int i = 0; i < 8; i++)
#pragma unroll
                for (int j = 0; j < 8; j++)
                    acc[i][j] = fmaf(a[i], b[j], acc[i][j]);
        }
        if (more) {
            buf ^= 1;
            As[buf][ac + 0][ar] = av.x; As[buf][ac + 1][ar] = av.y;
            As[buf][ac + 2][ar] = av.z; As[buf][ac + 3][ar] = av.w;
            Bs[buf][br][bc + 0] = bv.x; Bs[buf][br][bc + 1] = bv.y;
            Bs[buf][br][bc + 2] = bv.z; Bs[buf][br][bc + 3] = bv.w;
            __syncthreads();
        }
    }

#pragma unroll
    for (int i = 0; i < 8; i++) {
        int r = row0 + ty * 4 + (i & 3) + (i >> 2) * 64;
        if (r >= M) continue;
        float* cp = C + (size_t)r * Nc + col0;
        *(float4*)(cp + tx * 4)      = make_float4(acc[i][0], acc[i][1], acc[i][2], acc[i][3]);
        *(float4*)(cp + tx * 4 + 64) = make_float4(acc[i][4], acc[i][5], acc[i][6], acc[i][7]);
    }
}

// ======================= small SGEMM (64x64 tile) for final linear ==========
__global__ __launch_bounds__(256) void sgemm_bias64(
    const float* __restrict__ A, const float* __restrict__ B,
    const float* __restrict__ bias, float* __restrict__ C,
    int M, int K, int Nc)
{
    __shared__ float As[16][64];
    __shared__ float Bs[16][64];
    const int tid = threadIdx.x;
    const int tx = tid & 15, ty = tid >> 4;
    const int row0 = blockIdx.y * 64;
    const int col0 = blockIdx.x * 64;

    float acc[4][4];
#pragma unroll
    for (int i = 0; i < 4; i++)
#pragma unroll
        for (int j = 0; j < 4; j++) acc[i][j] = 0.f;

    const int ar = tid >> 2, ac = (tid & 3) * 4;
    const int br = tid >> 4, bc = (tid & 15) * 4;

    for (int k0 = 0; k0 < K; k0 += 16) {
        float4 av;
        if (row0 + ar < M) av = *(const float4*)(A + (size_t)(row0 + ar) * K + k0 + ac);
        else               av = make_float4(0.f, 0.f, 0.f, 0.f);
        As[ac + 0][ar] = av.x; As[ac + 1][ar] = av.y;
        As[ac + 2][ar] = av.z; As[ac + 3][ar] = av.w;
        float4 bv = *(const float4*)(B + (size_t)(k0 + br) * Nc + col0 + bc);
        Bs[br][bc + 0] = bv.x; Bs[br][bc + 1] = bv.y;
        Bs[br][bc + 2] = bv.z; Bs[br][bc + 3] = bv.w;
        __syncthreads();
#pragma unroll
        for (int k = 0; k < 16; k++) {
            float a[4], b[4];
#pragma unroll
            for (int i = 0; i < 4; i++) a[i] = As[k][ty * 4 + i];
#pragma unroll
            for (int j = 0; j < 4; j++) b[j] = Bs[k][tx * 4 + j];
#pragma unroll
            for (int i = 0; i < 4; i++)
#pragma unroll
                for (int j = 0; j < 4; j++) acc[i][j] = fmaf(a[i], b[j], acc[i][j]);
        }
        __syncthreads();
    }
#pragma unroll
    for (int i = 0; i < 4; i++) {
        int rr = row0 + ty * 4 + i;
        if (rr >= M) continue;
#pragma unroll
        for (int j = 0; j < 4; j++) {
            int cc = col0 + tx * 4 + j;
            C[(size_t)rr * Nc + cc] = acc[i][j] + bias[cc];
        }
    }
}

// ======================= fused node softmax + aggregation ====================
// One warp per destination node. Single pass over in-edges with online
// (flash-style) softmax: each xl[src] row is loaded ONCE and used for both the
// GATv2 score and the weighted accumulation. No atomics, no score storage.
template <int H, int C, bool ELU>
__global__ __launch_bounds__(256) void node_agg(
    const float* __restrict__ xlr, const int* __restrict__ rowp,
    const int* __restrict__ csrc, const float* __restrict__ att,
    const float* __restrict__ bias, float* __restrict__ out, int n)
{
    constexpr int HC  = H * C;
    constexpr int W2  = 2 * HC;
    constexpr int PL  = HC / 32;   // channels per lane
    constexpr int LPH = 32 / H;    // lanes per head

    int nid = blockIdx.x * 8 + (threadIdx.x >> 5);
    if (nid >= n) return;
    int lane = threadIdx.x & 31;

    int row = rowp[nid];
    int end = rowp[nid + 1];

    float rxr[PL], ratt[PL];
    {
        const float* xrp  = xlr + (size_t)nid * W2 + HC + lane * PL;
        const float* attp = att + lane * PL;
        if constexpr (PL == 8) {
            float4 a = *(const float4*)(xrp);
            float4 b = *(const float4*)(xrp + 4);
            rxr[0]=a.x; rxr[1]=a.y; rxr[2]=a.z; rxr[3]=a.w;
            rxr[4]=b.x; rxr[5]=b.y; rxr[6]=b.z; rxr[7]=b.w;
            float4 c = *(const float4*)(attp);
            float4 d = *(const float4*)(attp + 4);
            ratt[0]=c.x; ratt[1]=c.y; ratt[2]=c.z; ratt[3]=c.w;
            ratt[4]=d.x; ratt[5]=d.y; ratt[6]=d.z; ratt[7]=d.w;
        } else {
            float2 a = *(const float2*)(xrp);
            rxr[0]=a.x; rxr[1]=a.y;
            float2 c = *(const float2*)(attp);
            ratt[0]=c.x; ratt[1]=c.y;
        }
    }

    float m = -INFINITY, s = 0.f;
    float acc[PL];
#pragma unroll
    for (int j = 0; j < PL; j++) acc[j] = 0.f;

    for (int i = row; i < end; i++) {
        int sidx = csrc[i];
        const float* plp = xlr + (size_t)sidx * W2 + lane * PL;
        float pl[PL];
        if constexpr (PL == 8) {
            float4 a = *(const float4*)(plp);
            float4 b = *(const float4*)(plp + 4);
            pl[0]=a.x; pl[1]=a.y; pl[2]=a.z; pl[3]=a.w;
            pl[4]=b.x; pl[5]=b.y; pl[6]=b.z; pl[7]=b.w;
        } else {
            float2 a = *(const float2*)(plp);
            pl[0]=a.x; pl[1]=a.y;
        }

        float partial = 0.f;
#pragma unroll
        for (int j = 0; j < PL; j++) {
            float v = pl[j] + rxr[j];
            v = fmaxf(v, 0.2f * v);            // LeakyReLU(0.2)
            partial = fmaf(ratt[j], v, partial);
        }
#pragma unroll
        for (int o = LPH / 2; o > 0; o >>= 1)
            partial += __shfl_xor_sync(0xffffffffu, partial, o);
        // all lanes of this head now hold the edge score

        if (partial > m) {
            float sc = expf(m - partial);      // m = -inf on first edge -> 0
            s *= sc;
#pragma unroll
            for (int j = 0; j < PL; j++) acc[j] *= sc;
            m = partial;
        }
        float w = expf(partial - m);
        s += w;
#pragma unroll
        for (int j = 0; j < PL; j++) acc[j] = fmaf(w, pl[j], acc[j]);
    }

    float inv = 1.f / (s + 1e-16f);
    float* op = out + (size_t)nid * HC + lane * PL;
    const float* bp = bias + lane * PL;
#pragma unroll
    for (int j = 0; j < PL; j++) {
        float v = acc[j] * inv + bp[j];
        if constexpr (ELU) v = v > 0.f ? v : expm1f(v);
        op[j] = v;
    }
}

// ======================= host driver =========================================
extern "C" void kernel_launch(void* const* d_in, const int* in_sizes, int n_in,
                              void* d_out, int out_size)
{
    const float* x    = (const float*)d_in[0];
    const float* Wl1  = (const float*)d_in[1];
    const float* Wr1  = (const float*)d_in[2];
    const float* att1 = (const float*)d_in[3];
    const float* b1   = (const float*)d_in[4];
    const float* Wl2  = (const float*)d_in[5];
    const float* Wr2  = (const float*)d_in[6];
    const float* att2 = (const float*)d_in[7];
    const float* b2   = (const float*)d_in[8];
    const float* Wl3  = (const float*)d_in[9];
    const float* Wr3  = (const float*)d_in[10];
    const float* att3 = (const float*)d_in[11];
    const float* b3   = (const float*)d_in[12];
    const float* Wlin = (const float*)d_in[13];
    const float* blin = (const float*)d_in[14];
    const int*   ei   = (const int*)d_in[15];

    const int* src = ei;
    const int* dst = ei + NEDGES;

    void* tp;
    float *xlr, *h, *W;
    int *deg, *rowp, *pos, *csrc;
    cudaGetSymbolAddress(&tp, g_xlr);  xlr  = (float*)tp;
    cudaGetSymbolAddress(&tp, g_h);    h    = (float*)tp;
    cudaGetSymbolAddress(&tp, g_W);    W    = (float*)tp;
    cudaGetSymbolAddress(&tp, g_deg);  deg  = (int*)tp;
    cudaGetSymbolAddress(&tp, g_rowp); rowp = (int*)tp;
    cudaGetSymbolAddress(&tp, g_pos);  pos  = (int*)tp;
    cudaGetSymbolAddress(&tp, g_csrc); csrc = (int*)tp;

    // ---- CSR build (once; reused by all 3 layers) ----
    cudaMemsetAsync(deg, 0, (size_t)(NNODES + 1) * sizeof(int), 0);
    hist_kernel<<<(NEDGES + 255) / 256, 256>>>(dst, deg, NEDGES);
    scan_kernel<<<1, 1024>>>(deg, rowp, pos, NNODES, NEDGES);
    fillcsr_kernel<<<(NEDGES + 255) / 256, 256>>>(src, dst, pos, csrc, NEDGES);

    const int NB = (NNODES + 7) / 8;                     // node_agg blocks
    const dim3 gBig(4, (NNODES + 127) / 128);            // Nc=512
    const dim3 gSm (1, (NNODES + 127) / 128);            // Nc=128

    // ---- Layer 1: 128 -> 4x64, ELU ----
    pack2_kernel<<<(128 * 256 + 255) / 256, 256>>>(Wl1, Wr1, W, 128, 256);
    sgemm128<<<gBig, 256>>>(x, W, xlr, NNODES, 128, 512);
    node_agg<4, 64, true><<<NB, 256>>>(xlr, rowp, csrc, att1, b1, h, NNODES);

    // ---- Layer 2: 256 -> 4x64, ELU ----
    pack2_kernel<<<(256 * 256 + 255) / 256, 256>>>(Wl2, Wr2, W, 256, 256);
    sgemm128<<<gBig, 256>>>(h, W, xlr, NNODES, 256, 512);
    node_agg<4, 64, true><<<NB, 256>>>(xlr, rowp, csrc, att2, b2, h, NNODES);

    // ---- Layer 3: 256 -> 1x64, no activation ----
    pack2_kernel<<<(256 * 64 + 255) / 256, 256>>>(Wl3, Wr3, W, 256, 64);
    sgemm128<<<gSm, 256>>>(h, W, xlr, NNODES, 256, 128);
    node_agg<1, 64, false><<<NB, 256>>>(xlr, rowp, csrc, att3, b3, h, NNODES);

    // ---- Final linear: out = h @ Wlin + blin (50000x64 @ 64x64) ----
    dim3 gf(1, (NNODES + 63) / 64);
    sgemm_bias64<<<gf, 256>>>(h, Wlin, blin, (float*)d_out, NNODES, 64, 64);
}

// round 4
// speedup vs baseline: 4.8082x; 1.4710x over previous
#include <cuda_runtime.h>
#include <cuda_bf16.h>
#include <math.h>
#include <stdint.h>

#define NNODES 50000
#define NEDGES 800000
#define MT_PAD 3128          // ceil(50048/16): m16-tiles padded to CTA(128) multiple
#define KT_MAX 16            // K up to 256
#define NT16_MAX 32          // N up to 512

// ---------------- scratch (static device globals; no runtime allocation) ----
__device__ float g_xlr[(size_t)NNODES * 512];   // fused [xl | xr] gemm output
__device__ float g_h  [(size_t)NNODES * 256];   // layer activations
// fragment-major bf16 operands (hi/lo split)
__device__ uint4 g_Ah[(size_t)MT_PAD * KT_MAX * 32];
__device__ uint4 g_Al[(size_t)MT_PAD * KT_MAX * 32];
__device__ uint4 g_Bh[(size_t)NT16_MAX * KT_MAX * 32];
__device__ uint4 g_Bl[(size_t)NT16_MAX * KT_MAX * 32];
__device__ int   g_deg [NNODES + 1];
__device__ int   g_rowp[NNODES + 1];
__device__ int   g_pos [NNODES];
__device__ int   g_csrc[NEDGES];

// ======================= helpers ============================================
__device__ __forceinline__ uint32_t pack_bf16(float a, float b) { // a->low, b->high
    __nv_bfloat162 t;
    t.x = __float2bfloat16(a);
    t.y = __float2bfloat16(b);
    return *reinterpret_cast<uint32_t*>(&t);
}

__device__ __forceinline__ void mma16816(float* d, const uint4& a,
                                         uint32_t b0, uint32_t b1) {
    asm volatile(
        "mma.sync.aligned.m16n8k16.row.col.f32.bf16.bf16.f32 "
        "{%0,%1,%2,%3}, {%4,%5,%6,%7}, {%8,%9}, {%0,%1,%2,%3};"
        : "+f"(d[0]), "+f"(d[1]), "+f"(d[2]), "+f"(d[3])
        : "r"(a.x), "r"(a.y), "r"(a.z), "r"(a.w), "r"(b0), "r"(b1));
}

// ======================= CSR build ==========================================
__global__ void hist_kernel(const int* __restrict__ dst, int* __restrict__ deg, int E) {
    int i = blockIdx.x * blockDim.x + threadIdx.x;
    if (i < E) atomicAdd(&deg[dst[i]], 1);
}

__global__ void scan_kernel(const int* __restrict__ deg, int* __restrict__ rowp,
                            int* __restrict__ pos, int n, int E) {
    __shared__ int sums[1024];
    const int tid = threadIdx.x;
    const int CH = (n + 1023) / 1024;
    const int start = tid * CH;
    int local = 0;
    for (int i = 0; i < CH; i++) {
        int idx = start + i;
        if (idx < n) local += deg[idx];
    }
    sums[tid] = local;
    __syncthreads();
    for (int off = 1; off < 1024; off <<= 1) {
        int v = (tid >= off) ? sums[tid - off] : 0;
        __syncthreads();
        sums[tid] += v;
        __syncthreads();
    }
    int prefix = (tid == 0) ? 0 : sums[tid - 1];
    for (int i = 0; i < CH; i++) {
        int idx = start + i;
        if (idx < n) {
            rowp[idx] = prefix;
            pos[idx]  = prefix;
            prefix += deg[idx];
        }
    }
    if (tid == 1023) rowp[n] = E;
}

__global__ void fillcsr_kernel(const int* __restrict__ src, const int* __restrict__ dst,
                               int* __restrict__ pos, int* __restrict__ csrc, int E) {
    int i = blockIdx.x * blockDim.x + threadIdx.x;
    if (i < E) {
        int p = atomicAdd(&pos[dst[i]], 1);
        csrc[p] = src[i];
    }
}

// ========== A split+pack: fp32 [M][K] -> hi/lo bf16 fragment-major ==========
// block index (mt, kt), 32 lanes per block; lane's 4 regs contiguous (uint4).
// a0=(g, 2l,2l+1)  a1=(g+8, 2l,2l+1)  a2=(g, 2l+8,+9)  a3=(g+8, 2l+8,+9)
__global__ void splitA_frag(const float* __restrict__ A,
                            uint4* __restrict__ Ah, uint4* __restrict__ Al,
                            int M, int Kt) {
    int i = blockIdx.x * blockDim.x + threadIdx.x;
    int blk = i >> 5, lane = i & 31;
    int nblk = gridDim.x * blockDim.x >> 5;  // exact: launched to cover Mt_pad*Kt
    (void)nblk;
    int mt = blk / Kt, kt = blk - mt * Kt;
    if (mt >= MT_PAD) return;
    int g = lane >> 2, l = lane & 3;
    int K = Kt * 16;
    int r0 = mt * 16 + g, r1 = r0 + 8;
    int c0 = kt * 16 + 2 * l, c2 = c0 + 8;

    float2 v00 = make_float2(0.f, 0.f), v10 = v00, v02 = v00, v12 = v00;
    if (r0 < M) {
        v00 = *(const float2*)(A + (size_t)r0 * K + c0);
        v02 = *(const float2*)(A + (size_t)r0 * K + c2);
    }
    if (r1 < M) {
        v10 = *(const float2*)(A + (size_t)r1 * K + c0);
        v12 = *(const float2*)(A + (size_t)r1 * K + c2);
    }

    // hi parts
    float h00x = __bfloat162float(__float2bfloat16(v00.x));
    float h00y = __bfloat162float(__float2bfloat16(v00.y));
    float h10x = __bfloat162float(__float2bfloat16(v10.x));
    float h10y = __bfloat162float(__float2bfloat16(v10.y));
    float h02x = __bfloat162float(__float2bfloat16(v02.x));
    float h02y = __bfloat162float(__float2bfloat16(v02.y));
    float h12x = __bfloat162float(__float2bfloat16(v12.x));
    float h12y = __bfloat162float(__float2bfloat16(v12.y));

    uint4 hi, lo;
    hi.x = pack_bf16(v00.x, v00.y);
    hi.y = pack_bf16(v10.x, v10.y);
    hi.z = pack_bf16(v02.x, v02.y);
    hi.w = pack_bf16(v12.x, v12.y);
    lo.x = pack_bf16(v00.x - h00x, v00.y - h00y);
    lo.y = pack_bf16(v10.x - h10x, v10.y - h10y);
    lo.z = pack_bf16(v02.x - h02x, v02.y - h02y);
    lo.w = pack_bf16(v12.x - h12x, v12.y - h12y);

    size_t off = (size_t)blk * 32 + lane;
    Ah[off] = hi;
    Al[off] = lo;
}

// ========== B pack: [Wl|Wr] ([K][HC] each) -> hi/lo fragment-major ==========
// block (nt16, kt): r0,r1 = n8#0 (col n0+g), r2,r3 = n8#1 (col n0+8+g)
// b0 = {B[k0+2l][c], B[k0+2l+1][c]}, b1 = {B[k0+2l+8][c], B[k0+2l+9][c]}
__global__ void packB_frag(const float* __restrict__ Wl, const float* __restrict__ Wr,
                           uint4* __restrict__ Bh, uint4* __restrict__ Bl,
                           int Kt, int HC) {
    int i = blockIdx.x * blockDim.x + threadIdx.x;
    int blk = i >> 5, lane = i & 31;
    int nt16 = blk / Kt, kt = blk - nt16 * Kt;
    int N2 = 2 * HC;
    if (nt16 * 16 >= N2) return;
    int g = lane >> 2, l = lane & 3;
    int k0 = kt * 16 + 2 * l;

    uint4 hi, lo;
    uint32_t* hp = &hi.x;
    uint32_t* lp = &lo.x;
#pragma unroll
    for (int half = 0; half < 2; half++) {
        int col = nt16 * 16 + half * 8 + g;
        const float* Wt = (col < HC) ? Wl : Wr;
        int c = (col < HC) ? col : col - HC;
#pragma unroll
        for (int r = 0; r < 2; r++) {
            int k = k0 + r * 8;
            float a = Wt[(size_t)k * HC + c];
            float b = Wt[(size_t)(k + 1) * HC + c];
            float ha = __bfloat162float(__float2bfloat16(a));
            float hb = __bfloat162float(__float2bfloat16(b));
            hp[half * 2 + r] = pack_bf16(a, b);
            lp[half * 2 + r] = pack_bf16(a - ha, b - hb);
        }
    }
    size_t off = (size_t)blk * 32 + lane;
    Bh[off] = hi;
    Bl[off] = lo;
}

// ======================= HMMA GEMM (3-term bf16 split) ======================
// C[M,N2] = (Ah+Al)(Bh+Bl)^T, dropping AlBl. CTA tile 128x128, warp 32x64.
// No smem, no syncs: fragments read straight from L2-resident frag buffers.
__global__ __launch_bounds__(256, 2) void mma_gemm(
    const uint4* __restrict__ Ah, const uint4* __restrict__ Al,
    const uint4* __restrict__ Bh, const uint4* __restrict__ Bl,
    float* __restrict__ C, int M, int Kt, int N2)
{
    const int tid = threadIdx.x;
    const int wid = tid >> 5, lane = tid & 31;
    const int g = lane >> 2, l = lane & 3;
    const int mw = wid & 3, nw = wid >> 2;

    const int mt0  = blockIdx.y * 8 + mw * 2;   // 2 m16 tiles per warp
    const int nt0  = blockIdx.x * 8 + nw * 4;   // 4 n16 tiles per warp

    float acc[2][8][4];
#pragma unroll
    for (int i = 0; i < 2; i++)
#pragma unroll
        for (int j = 0; j < 8; j++)
#pragma unroll
            for (int r = 0; r < 4; r++) acc[i][j][r] = 0.f;

    const uint4* pa0 = Ah + ((size_t)(mt0)     * Kt) * 32 + lane;
    const uint4* pa1 = Ah + ((size_t)(mt0 + 1) * Kt) * 32 + lane;
    const uint4* qa0 = Al + ((size_t)(mt0)     * Kt) * 32 + lane;
    const uint4* qa1 = Al + ((size_t)(mt0 + 1) * Kt) * 32 + lane;

    for (int kt = 0; kt < Kt; kt++) {
        uint4 ah[2], al[2];
        ah[0] = pa0[kt * 32]; ah[1] = pa1[kt * 32];
        al[0] = qa0[kt * 32]; al[1] = qa1[kt * 32];

        uint4 bh[4], bl[4];
#pragma unroll
        for (int j = 0; j < 4; j++) {
            size_t off = ((size_t)(nt0 + j) * Kt + kt) * 32 + lane;
            bh[j] = Bh[off];
            bl[j] = Bl[off];
        }

#pragma unroll
        for (int i = 0; i < 2; i++)
#pragma unroll
            for (int j = 0; j < 4; j++) {
                // term AhBh
                mma16816(acc[i][2 * j],     ah[i], bh[j].x, bh[j].y);
                mma16816(acc[i][2 * j + 1], ah[i], bh[j].z, bh[j].w);
                // term AhBl
                mma16816(acc[i][2 * j],     ah[i], bl[j].x, bl[j].y);
                mma16816(acc[i][2 * j + 1], ah[i], bl[j].z, bl[j].w);
                // term AlBh
                mma16816(acc[i][2 * j],     al[i], bh[j].x, bh[j].y);
                mma16816(acc[i][2 * j + 1], al[i], bh[j].z, bh[j].w);
            }
    }

    // epilogue: c0,c1 = (row g, cols 2l,2l+1); c2,c3 = (row g+8, same cols)
#pragma unroll
    for (int i = 0; i < 2; i++) {
        int rbase = (mt0 + i) * 16;
#pragma unroll
        for (int j = 0; j < 8; j++) {
            int col = (nt0 + (j >> 1)) * 16 + (j & 1) * 8 + 2 * l;
            int r0 = rbase + g, r1 = rbase + g + 8;
            if (r0 < M)
                *(float2*)(C + (size_t)r0 * N2 + col) =
                    make_float2(acc[i][j][0], acc[i][j][1]);
            if (r1 < M)
                *(float2*)(C + (size_t)r1 * N2 + col) =
                    make_float2(acc[i][j][2], acc[i][j][3]);
        }
    }
}

// ======================= small SGEMM (64x64) for final linear ===============
__global__ __launch_bounds__(256) void sgemm_bias64(
    const float* __restrict__ A, const float* __restrict__ B,
    const float* __restrict__ bias, float* __restrict__ C,
    int M, int K, int Nc)
{
    __shared__ float As[16][64];
    __shared__ float Bs[16][64];
    const int tid = threadIdx.x;
    const int tx = tid & 15, ty = tid >> 4;
    const int row0 = blockIdx.y * 64;
    const int col0 = blockIdx.x * 64;

    float acc[4][4];
#pragma unroll
    for (int i = 0; i < 4; i++)
#pragma unroll
        for (int j = 0; j < 4; j++) acc[i][j] = 0.f;

    const int ar = tid >> 2, ac = (tid & 3) * 4;
    const int br = tid >> 4, bc = (tid & 15) * 4;

    for (int k0 = 0; k0 < K; k0 += 16) {
        float4 av;
        if (row0 + ar < M) av = *(const float4*)(A + (size_t)(row0 + ar) * K + k0 + ac);
        else               av = make_float4(0.f, 0.f, 0.f, 0.f);
        As[ac + 0][ar] = av.x; As[ac + 1][ar] = av.y;
        As[ac + 2][ar] = av.z; As[ac + 3][ar] = av.w;
        float4 bv = *(const float4*)(B + (size_t)(k0 + br) * Nc + col0 + bc);
        Bs[br][bc + 0] = bv.x; Bs[br][bc + 1] = bv.y;
        Bs[br][bc + 2] = bv.z; Bs[br][bc + 3] = bv.w;
        __syncthreads();
#pragma unroll
        for (int k = 0; k < 16; k++) {
            float a[4], b[4];
#pragma unroll
            for (int i = 0; i < 4; i++) a[i] = As[k][ty * 4 + i];
#pragma unroll
            for (int j = 0; j < 4; j++) b[j] = Bs[k][tx * 4 + j];
#pragma unroll
            for (int i = 0; i < 4; i++)
#pragma unroll
                for (int j = 0; j < 4; j++) acc[i][j] = fmaf(a[i], b[j], acc[i][j]);
        }
        __syncthreads();
    }
#pragma unroll
    for (int i = 0; i < 4; i++) {
        int rr = row0 + ty * 4 + i;
        if (rr >= M) continue;
#pragma unroll
        for (int j = 0; j < 4; j++) {
            int cc = col0 + tx * 4 + j;
            C[(size_t)rr * Nc + cc] = acc[i][j] + bias[cc];
        }
    }
}

// ======================= fused node softmax + aggregation ====================
template <int H, int C, bool ELU>
__global__ __launch_bounds__(256) void node_agg(
    const float* __restrict__ xlr, const int* __restrict__ rowp,
    const int* __restrict__ csrc, const float* __restrict__ att,
    const float* __restrict__ bias, float* __restrict__ out, int n)
{
    constexpr int HC  = H * C;
    constexpr int W2  = 2 * HC;
    constexpr int PL  = HC / 32;
    constexpr int LPH = 32 / H;

    int nid = blockIdx.x * 8 + (threadIdx.x >> 5);
    if (nid >= n) return;
    int lane = threadIdx.x & 31;

    int row = rowp[nid];
    int end = rowp[nid + 1];

    float rxr[PL], ratt[PL];
    {
        const float* xrp  = xlr + (size_t)nid * W2 + HC + lane * PL;
        const float* attp = att + lane * PL;
        if constexpr (PL == 8) {
            float4 a = *(const float4*)(xrp);
            float4 b = *(const float4*)(xrp + 4);
            rxr[0]=a.x; rxr[1]=a.y; rxr[2]=a.z; rxr[3]=a.w;
            rxr[4]=b.x; rxr[5]=b.y; rxr[6]=b.z; rxr[7]=b.w;
            float4 c = *(const float4*)(attp);
            float4 d = *(const float4*)(attp + 4);
            ratt[0]=c.x; ratt[1]=c.y; ratt[2]=c.z; ratt[3]=c.w;
            ratt[4]=d.x; ratt[5]=d.y; ratt[6]=d.z; ratt[7]=d.w;
        } else {
            float2 a = *(const float2*)(xrp);
            rxr[0]=a.x; rxr[1]=a.y;
            float2 c = *(const float2*)(attp);
            ratt[0]=c.x; ratt[1]=c.y;
        }
    }

    float m = -INFINITY, s = 0.f;
    float acc[PL];
#pragma unroll
    for (int j = 0; j < PL; j++) acc[j] = 0.f;

    for (int i = row; i < end; i++) {
        int sidx = csrc[i];
        const float* plp = xlr + (size_t)sidx * W2 + lane * PL;
        float pl[PL];
        if constexpr (PL == 8) {
            float4 a = *(const float4*)(plp);
            float4 b = *(const float4*)(plp + 4);
            pl[0]=a.x; pl[1]=a.y; pl[2]=a.z; pl[3]=a.w;
            pl[4]=b.x; pl[5]=b.y; pl[6]=b.z; pl[7]=b.w;
        } else {
            float2 a = *(const float2*)(plp);
            pl[0]=a.x; pl[1]=a.y;
        }

        float partial = 0.f;
#pragma unroll
        for (int j = 0; j < PL; j++) {
            float v = pl[j] + rxr[j];
            v = fmaxf(v, 0.2f * v);
            partial = fmaf(ratt[j], v, partial);
        }
#pragma unroll
        for (int o = LPH / 2; o > 0; o >>= 1)
            partial += __shfl_xor_sync(0xffffffffu, partial, o);

        if (partial > m) {
            float sc = expf(m - partial);
            s *= sc;
#pragma unroll
            for (int j = 0; j < PL; j++) acc[j] *= sc;
            m = partial;
        }
        float w = expf(partial - m);
        s += w;
#pragma unroll
        for (int j = 0; j < PL; j++) acc[j] = fmaf(w, pl[j], acc[j]);
    }

    float inv = 1.f / (s + 1e-16f);
    float* op = out + (size_t)nid * HC + lane * PL;
    const float* bp = bias + lane * PL;
#pragma unroll
    for (int j = 0; j < PL; j++) {
        float v = acc[j] * inv + bp[j];
        if constexpr (ELU) v = v > 0.f ? v : expm1f(v);
        op[j] = v;
    }
}

// ======================= host driver =========================================
extern "C" void kernel_launch(void* const* d_in, const int* in_sizes, int n_in,
                              void* d_out, int out_size)
{
    const float* x    = (const float*)d_in[0];
    const float* Wl1  = (const float*)d_in[1];
    const float* Wr1  = (const float*)d_in[2];
    const float* att1 = (const float*)d_in[3];
    const float* b1   = (const float*)d_in[4];
    const float* Wl2  = (const float*)d_in[5];
    const float* Wr2  = (const float*)d_in[6];
    const float* att2 = (const float*)d_in[7];
    const float* b2   = (const float*)d_in[8];
    const float* Wl3  = (const float*)d_in[9];
    const float* Wr3  = (const float*)d_in[10];
    const float* att3 = (const float*)d_in[11];
    const float* b3   = (const float*)d_in[12];
    const float* Wlin = (const float*)d_in[13];
    const float* blin = (const float*)d_in[14];
    const int*   ei   = (const int*)d_in[15];

    const int* src = ei;
    const int* dst = ei + NEDGES;

    void* tp;
    float *xlr, *h;
    uint4 *Ah, *Al, *Bh, *Bl;
    int *deg, *rowp, *pos, *csrc;
    cudaGetSymbolAddress(&tp, g_xlr);  xlr  = (float*)tp;
    cudaGetSymbolAddress(&tp, g_h);    h    = (float*)tp;
    cudaGetSymbolAddress(&tp, g_Ah);   Ah   = (uint4*)tp;
    cudaGetSymbolAddress(&tp, g_Al);   Al   = (uint4*)tp;
    cudaGetSymbolAddress(&tp, g_Bh);   Bh   = (uint4*)tp;
    cudaGetSymbolAddress(&tp, g_Bl);   Bl   = (uint4*)tp;
    cudaGetSymbolAddress(&tp, g_deg);  deg  = (int*)tp;
    cudaGetSymbolAddress(&tp, g_rowp); rowp = (int*)tp;
    cudaGetSymbolAddress(&tp, g_pos);  pos  = (int*)tp;
    cudaGetSymbolAddress(&tp, g_csrc); csrc = (int*)tp;

    // ---- CSR build (once; reused by all 3 layers) ----
    cudaMemsetAsync(deg, 0, (size_t)(NNODES + 1) * sizeof(int), 0);
    hist_kernel<<<(NEDGES + 255) / 256, 256>>>(dst, deg, NEDGES);
    scan_kernel<<<1, 1024>>>(deg, rowp, pos, NNODES, NEDGES);
    fillcsr_kernel<<<(NEDGES + 255) / 256, 256>>>(src, dst, pos, csrc, NEDGES);

    const int NB = (NNODES + 7) / 8;
    const int MTB = (NNODES + 127) / 128;   // 391 CTA rows

    // ---- Layer 1: K=128 (Kt=8) -> N2=512, ELU ----
    {
        int Kt = 8, HC = 256, N2 = 512;
        int athr = MT_PAD * Kt * 32;
        splitA_frag<<<(athr + 255) / 256, 256>>>(x, Ah, Al, NNODES, Kt);
        int bthr = (N2 / 16) * Kt * 32;
        packB_frag<<<(bthr + 255) / 256, 256>>>(Wl1, Wr1, Bh, Bl, Kt, HC);
        mma_gemm<<<dim3(N2 / 128, MTB), 256>>>(Ah, Al, Bh, Bl, xlr, NNODES, Kt, N2);
        node_agg<4, 64, true><<<NB, 256>>>(xlr, rowp, csrc, att1, b1, h, NNODES);
    }
    // ---- Layer 2: K=256 (Kt=16) -> N2=512, ELU ----
    {
        int Kt = 16, HC = 256, N2 = 512;
        int athr = MT_PAD * Kt * 32;
        splitA_frag<<<(athr + 255) / 256, 256>>>(h, Ah, Al, NNODES, Kt);
        int bthr = (N2 / 16) * Kt * 32;
        packB_frag<<<(bthr + 255) / 256, 256>>>(Wl2, Wr2, Bh, Bl, Kt, HC);
        mma_gemm<<<dim3(N2 / 128, MTB), 256>>>(Ah, Al, Bh, Bl, xlr, NNODES, Kt, N2);
        node_agg<4, 64, true><<<NB, 256>>>(xlr, rowp, csrc, att2, b2, h, NNODES);
    }
    // ---- Layer 3: K=256 (Kt=16) -> N2=128, no activation ----
    {
        int Kt = 16, HC = 64, N2 = 128;
        int athr = MT_PAD * Kt * 32;
        splitA_frag<<<(athr + 255) / 256, 256>>>(h, Ah, Al, NNODES, Kt);
        int bthr = (N2 / 16) * Kt * 32;
        packB_frag<<<(bthr + 255) / 256, 256>>>(Wl3, Wr3, Bh, Bl, Kt, HC);
        mma_gemm<<<dim3(N2 / 128, MTB), 256>>>(Ah, Al, Bh, Bl, xlr, NNODES, Kt, N2);
        node_agg<1, 64, false><<<NB, 256>>>(xlr, rowp, csrc, att3, b3, h, NNODES);
    }

    // ---- Final linear: out = h @ Wlin + blin (50000x64 @ 64x64) ----
    dim3 gf(1, (NNODES + 63) / 64);
    sgemm_bias64<<<gf, 256>>>(h, Wlin, blin, (float*)d_out, NNODES, 64, 64);
}

// round 5
// speedup vs baseline: 4.9639x; 1.0324x over previous
#include <cuda_runtime.h>
#include <cuda_bf16.h>
#include <math.h>
#include <stdint.h>

#define NNODES 50000
#define NEDGES 800000
#define MT_PAD 3128          // ceil(50048/16): m16-tiles padded to CTA(128) multiple
#define KT_MAX 16            // K up to 256
#define NT16_MAX 32          // N up to 512

// ---------------- scratch (static device globals; no runtime allocation) ----
__device__ float g_xlr[(size_t)NNODES * 512];   // fused [xl | xr] gemm output
__device__ float g_h  [(size_t)NNODES * 256];   // layer activations
// fragment-major bf16 operands (hi/lo split)
__device__ uint4 g_Ah[(size_t)MT_PAD * KT_MAX * 32];
__device__ uint4 g_Al[(size_t)MT_PAD * KT_MAX * 32];
__device__ uint4 g_Bh[(size_t)NT16_MAX * KT_MAX * 32];
__device__ uint4 g_Bl[(size_t)NT16_MAX * KT_MAX * 32];
__device__ int   g_deg [NNODES + 1];
__device__ int   g_rowp[NNODES + 1];
__device__ int   g_pos [NNODES];
__device__ int   g_csrc[NEDGES];

// ======================= helpers ============================================
__device__ __forceinline__ uint32_t pack_bf16(float a, float b) { // a->low, b->high
    __nv_bfloat162 t;
    t.x = __float2bfloat16(a);
    t.y = __float2bfloat16(b);
    return *reinterpret_cast<uint32_t*>(&t);
}

__device__ __forceinline__ void mma16816(float* d, const uint4& a,
                                         uint32_t b0, uint32_t b1) {
    asm volatile(
        "mma.sync.aligned.m16n8k16.row.col.f32.bf16.bf16.f32 "
        "{%0,%1,%2,%3}, {%4,%5,%6,%7}, {%8,%9}, {%0,%1,%2,%3};"
        : "+f"(d[0]), "+f"(d[1]), "+f"(d[2]), "+f"(d[3])
        : "r"(a.x), "r"(a.y), "r"(a.z), "r"(a.w), "r"(b0), "r"(b1));
}

// ======================= CSR build ==========================================
__global__ void hist_kernel(const int* __restrict__ dst, int* __restrict__ deg, int E) {
    int i = blockIdx.x * blockDim.x + threadIdx.x;
    if (i < E) atomicAdd(&deg[dst[i]], 1);
}

__global__ void scan_kernel(const int* __restrict__ deg, int* __restrict__ rowp,
                            int* __restrict__ pos, int n, int E) {
    __shared__ int sums[1024];
    const int tid = threadIdx.x;
    const int CH = (n + 1023) / 1024;
    const int start = tid * CH;
    int local = 0;
    for (int i = 0; i < CH; i++) {
        int idx = start + i;
        if (idx < n) local += deg[idx];
    }
    sums[tid] = local;
    __syncthreads();
    for (int off = 1; off < 1024; off <<= 1) {
        int v = (tid >= off) ? sums[tid - off] : 0;
        __syncthreads();
        sums[tid] += v;
        __syncthreads();
    }
    int prefix = (tid == 0) ? 0 : sums[tid - 1];
    for (int i = 0; i < CH; i++) {
        int idx = start + i;
        if (idx < n) {
            rowp[idx] = prefix;
            pos[idx]  = prefix;
            prefix += deg[idx];
        }
    }
    if (tid == 1023) rowp[n] = E;
}

__global__ void fillcsr_kernel(const int* __restrict__ src, const int* __restrict__ dst,
                               int* __restrict__ pos, int* __restrict__ csrc, int E) {
    int i = blockIdx.x * blockDim.x + threadIdx.x;
    if (i < E) {
        int p = atomicAdd(&pos[dst[i]], 1);
        csrc[p] = src[i];
    }
}

// ========== A split+pack: fp32 [M][K] -> hi/lo bf16 fragment-major ==========
__global__ void splitA_frag(const float* __restrict__ A,
                            uint4* __restrict__ Ah, uint4* __restrict__ Al,
                            int M, int Kt) {
    int i = blockIdx.x * blockDim.x + threadIdx.x;
    int blk = i >> 5, lane = i & 31;
    int mt = blk / Kt, kt = blk - mt * Kt;
    if (mt >= MT_PAD) return;
    int g = lane >> 2, l = lane & 3;
    int K = Kt * 16;
    int r0 = mt * 16 + g, r1 = r0 + 8;
    int c0 = kt * 16 + 2 * l, c2 = c0 + 8;

    float2 v00 = make_float2(0.f, 0.f), v10 = v00, v02 = v00, v12 = v00;
    if (r0 < M) {
        v00 = *(const float2*)(A + (size_t)r0 * K + c0);
        v02 = *(const float2*)(A + (size_t)r0 * K + c2);
    }
    if (r1 < M) {
        v10 = *(const float2*)(A + (size_t)r1 * K + c0);
        v12 = *(const float2*)(A + (size_t)r1 * K + c2);
    }

    float h00x = __bfloat162float(__float2bfloat16(v00.x));
    float h00y = __bfloat162float(__float2bfloat16(v00.y));
    float h10x = __bfloat162float(__float2bfloat16(v10.x));
    float h10y = __bfloat162float(__float2bfloat16(v10.y));
    float h02x = __bfloat162float(__float2bfloat16(v02.x));
    float h02y = __bfloat162float(__float2bfloat16(v02.y));
    float h12x = __bfloat162float(__float2bfloat16(v12.x));
    float h12y = __bfloat162float(__float2bfloat16(v12.y));

    uint4 hi, lo;
    hi.x = pack_bf16(v00.x, v00.y);
    hi.y = pack_bf16(v10.x, v10.y);
    hi.z = pack_bf16(v02.x, v02.y);
    hi.w = pack_bf16(v12.x, v12.y);
    lo.x = pack_bf16(v00.x - h00x, v00.y - h00y);
    lo.y = pack_bf16(v10.x - h10x, v10.y - h10y);
    lo.z = pack_bf16(v02.x - h02x, v02.y - h02y);
    lo.w = pack_bf16(v12.x - h12x, v12.y - h12y);

    size_t off = (size_t)blk * 32 + lane;
    Ah[off] = hi;
    Al[off] = lo;
}

// ========== B pack: [Wl|Wr] ([K][HC] each) -> hi/lo fragment-major ==========
__global__ void packB_frag(const float* __restrict__ Wl, const float* __restrict__ Wr,
                           uint4* __restrict__ Bh, uint4* __restrict__ Bl,
                           int Kt, int HC) {
    int i = blockIdx.x * blockDim.x + threadIdx.x;
    int blk = i >> 5, lane = i & 31;
    int nt16 = blk / Kt, kt = blk - nt16 * Kt;
    int N2 = 2 * HC;
    if (nt16 * 16 >= N2) return;
    int g = lane >> 2, l = lane & 3;
    int k0 = kt * 16 + 2 * l;

    uint4 hi, lo;
    uint32_t* hp = &hi.x;
    uint32_t* lp = &lo.x;
#pragma unroll
    for (int half = 0; half < 2; half++) {
        int col = nt16 * 16 + half * 8 + g;
        const float* Wt = (col < HC) ? Wl : Wr;
        int c = (col < HC) ? col : col - HC;
#pragma unroll
        for (int r = 0; r < 2; r++) {
            int k = k0 + r * 8;
            float a = Wt[(size_t)k * HC + c];
            float b = Wt[(size_t)(k + 1) * HC + c];
            float ha = __bfloat162float(__float2bfloat16(a));
            float hb = __bfloat162float(__float2bfloat16(b));
            hp[half * 2 + r] = pack_bf16(a, b);
            lp[half * 2 + r] = pack_bf16(a - ha, b - hb);
        }
    }
    size_t off = (size_t)blk * 32 + lane;
    Bh[off] = hi;
    Bl[off] = lo;
}

// ======================= HMMA GEMM (3-term bf16 split) ======================
// C[M,N2] = (Ah+Al)(Bh+Bl)^T, dropping AlBl. CTA tile 128x128, warp 32x64.
// Register software pipeline over kt; MMAs ordered term-outermost so each
// accumulator's reuse distance is 16 independent HMMAs.
__global__ __launch_bounds__(256) void mma_gemm(
    const uint4* __restrict__ Ah, const uint4* __restrict__ Al,
    const uint4* __restrict__ Bh, const uint4* __restrict__ Bl,
    float* __restrict__ C, int M, int Kt, int N2)
{
    const int tid = threadIdx.x;
    const int wid = tid >> 5, lane = tid & 31;
    const int g = lane >> 2, l = lane & 3;
    const int mw = wid & 3, nw = wid >> 2;

    const int mt0  = blockIdx.y * 8 + mw * 2;   // 2 m16 tiles per warp
    const int nt0  = blockIdx.x * 8 + nw * 4;   // 4 n16 tiles per warp

    float acc[2][8][4];
#pragma unroll
    for (int i = 0; i < 2; i++)
#pragma unroll
        for (int j = 0; j < 8; j++)
#pragma unroll
            for (int r = 0; r < 4; r++) acc[i][j][r] = 0.f;

    const uint4* pa0 = Ah + ((size_t)(mt0)     * Kt) * 32 + lane;
    const uint4* pa1 = Ah + ((size_t)(mt0 + 1) * Kt) * 32 + lane;
    const uint4* qa0 = Al + ((size_t)(mt0)     * Kt) * 32 + lane;
    const uint4* qa1 = Al + ((size_t)(mt0 + 1) * Kt) * 32 + lane;

    uint4 ah[2], al[2], bh[4], bl[4];
    // preload kt = 0
    ah[0] = pa0[0]; ah[1] = pa1[0];
    al[0] = qa0[0]; al[1] = qa1[0];
#pragma unroll
    for (int j = 0; j < 4; j++) {
        size_t off = ((size_t)(nt0 + j) * Kt) * 32 + lane;
        bh[j] = Bh[off];
        bl[j] = Bl[off];
    }

    for (int kt = 0; kt < Kt; kt++) {
        uint4 nah[2], nal[2], nbh[4], nbl[4];
        if (kt + 1 < Kt) {
            nah[0] = pa0[(kt + 1) * 32]; nah[1] = pa1[(kt + 1) * 32];
            nal[0] = qa0[(kt + 1) * 32]; nal[1] = qa1[(kt + 1) * 32];
#pragma unroll
            for (int j = 0; j < 4; j++) {
                size_t off = ((size_t)(nt0 + j) * Kt + kt + 1) * 32 + lane;
                nbh[j] = Bh[off];
                nbl[j] = Bl[off];
            }
        }

        // term AhBh
#pragma unroll
        for (int i = 0; i < 2; i++)
#pragma unroll
            for (int j = 0; j < 4; j++) {
                mma16816(acc[i][2 * j],     ah[i], bh[j].x, bh[j].y);
                mma16816(acc[i][2 * j + 1], ah[i], bh[j].z, bh[j].w);
            }
        // term AhBl
#pragma unroll
        for (int i = 0; i < 2; i++)
#pragma unroll
            for (int j = 0; j < 4; j++) {
                mma16816(acc[i][2 * j],     ah[i], bl[j].x, bl[j].y);
                mma16816(acc[i][2 * j + 1], ah[i], bl[j].z, bl[j].w);
            }
        // term AlBh
#pragma unroll
        for (int i = 0; i < 2; i++)
#pragma unroll
            for (int j = 0; j < 4; j++) {
                mma16816(acc[i][2 * j],     al[i], bh[j].x, bh[j].y);
                mma16816(acc[i][2 * j + 1], al[i], bh[j].z, bh[j].w);
            }

        if (kt + 1 < Kt) {
#pragma unroll
            for (int i = 0; i < 2; i++) { ah[i] = nah[i]; al[i] = nal[i]; }
#pragma unroll
            for (int j = 0; j < 4; j++) { bh[j] = nbh[j]; bl[j] = nbl[j]; }
        }
    }

    // epilogue: c0,c1 = (row g, cols 2l,2l+1); c2,c3 = (row g+8, same cols)
#pragma unroll
    for (int i = 0; i < 2; i++) {
        int rbase = (mt0 + i) * 16;
#pragma unroll
        for (int j = 0; j < 8; j++) {
            int col = (nt0 + (j >> 1)) * 16 + (j & 1) * 8 + 2 * l;
            int r0 = rbase + g, r1 = rbase + g + 8;
            if (r0 < M)
                *(float2*)(C + (size_t)r0 * N2 + col) =
                    make_float2(acc[i][j][0], acc[i][j][1]);
            if (r1 < M)
                *(float2*)(C + (size_t)r1 * N2 + col) =
                    make_float2(acc[i][j][2], acc[i][j][3]);
        }
    }
}

// ======================= small SGEMM (64x64) for final linear ===============
__global__ __launch_bounds__(256) void sgemm_bias64(
    const float* __restrict__ A, const float* __restrict__ B,
    const float* __restrict__ bias, float* __restrict__ C,
    int M, int K, int Nc)
{
    __shared__ float As[16][64];
    __shared__ float Bs[16][64];
    const int tid = threadIdx.x;
    const int tx = tid & 15, ty = tid >> 4;
    const int row0 = blockIdx.y * 64;
    const int col0 = blockIdx.x * 64;

    float acc[4][4];
#pragma unroll
    for (int i = 0; i < 4; i++)
#pragma unroll
        for (int j = 0; j < 4; j++) acc[i][j] = 0.f;

    const int ar = tid >> 2, ac = (tid & 3) * 4;
    const int br = tid >> 4, bc = (tid & 15) * 4;

    for (int k0 = 0; k0 < K; k0 += 16) {
        float4 av;
        if (row0 + ar < M) av = *(const float4*)(A + (size_t)(row0 + ar) * K + k0 + ac);
        else               av = make_float4(0.f, 0.f, 0.f, 0.f);
        As[ac + 0][ar] = av.x; As[ac + 1][ar] = av.y;
        As[ac + 2][ar] = av.z; As[ac + 3][ar] = av.w;
        float4 bv = *(const float4*)(B + (size_t)(k0 + br) * Nc + col0 + bc);
        Bs[br][bc + 0] = bv.x; Bs[br][bc + 1] = bv.y;
        Bs[br][bc + 2] = bv.z; Bs[br][bc + 3] = bv.w;
        __syncthreads();
#pragma unroll
        for (int k = 0; k < 16; k++) {
            float a[4], b[4];
#pragma unroll
            for (int i = 0; i < 4; i++) a[i] = As[k][ty * 4 + i];
#pragma unroll
            for (int j = 0; j < 4; j++) b[j] = Bs[k][tx * 4 + j];
#pragma unroll
            for (int i = 0; i < 4; i++)
#pragma unroll
                for (int j = 0; j < 4; j++) acc[i][j] = fmaf(a[i], b[j], acc[i][j]);
        }
        __syncthreads();
    }
#pragma unroll
    for (int i = 0; i < 4; i++) {
        int rr = row0 + ty * 4 + i;
        if (rr >= M) continue;
#pragma unroll
        for (int j = 0; j < 4; j++) {
            int cc = col0 + tx * 4 + j;
            C[(size_t)rr * Nc + cc] = acc[i][j] + bias[cc];
        }
    }
}

// ======================= fused node softmax + aggregation ====================
// One warp per destination node; flash-style online softmax, edge loop
// unrolled x2 with both gathers issued before any dependent math.
template <int H, int C, bool ELU>
__global__ __launch_bounds__(256) void node_agg(
    const float* __restrict__ xlr, const int* __restrict__ rowp,
    const int* __restrict__ csrc, const float* __restrict__ att,
    const float* __restrict__ bias, float* __restrict__ out, int n)
{
    constexpr int HC  = H * C;
    constexpr int W2  = 2 * HC;
    constexpr int PL  = HC / 32;
    constexpr int LPH = 32 / H;

    int nid = blockIdx.x * 8 + (threadIdx.x >> 5);
    if (nid >= n) return;
    int lane = threadIdx.x & 31;

    int row = rowp[nid];
    int end = rowp[nid + 1];

    float rxr[PL], ratt[PL];
    {
        const float* xrp  = xlr + (size_t)nid * W2 + HC + lane * PL;
        const float* attp = att + lane * PL;
        if constexpr (PL == 8) {
            float4 a = *(const float4*)(xrp);
            float4 b = *(const float4*)(xrp + 4);
            rxr[0]=a.x; rxr[1]=a.y; rxr[2]=a.z; rxr[3]=a.w;
            rxr[4]=b.x; rxr[5]=b.y; rxr[6]=b.z; rxr[7]=b.w;
            float4 c = *(const float4*)(attp);
            float4 d = *(const float4*)(attp + 4);
            ratt[0]=c.x; ratt[1]=c.y; ratt[2]=c.z; ratt[3]=c.w;
            ratt[4]=d.x; ratt[5]=d.y; ratt[6]=d.z; ratt[7]=d.w;
        } else {
            float2 a = *(const float2*)(xrp);
            rxr[0]=a.x; rxr[1]=a.y;
            float2 c = *(const float2*)(attp);
            ratt[0]=c.x; ratt[1]=c.y;
        }
    }

    float m = -INFINITY, s = 0.f;
    float acc[PL];
#pragma unroll
    for (int j = 0; j < PL; j++) acc[j] = 0.f;

#define LOAD_PL(dst, sidx) do { \
    const float* _p = xlr + (size_t)(sidx) * W2 + lane * PL; \
    if constexpr (PL == 8) { \
        float4 _a = *(const float4*)(_p); \
        float4 _b = *(const float4*)(_p + 4); \
        dst[0]=_a.x; dst[1]=_a.y; dst[2]=_a.z; dst[3]=_a.w; \
        dst[4]=_b.x; dst[5]=_b.y; dst[6]=_b.z; dst[7]=_b.w; \
    } else { \
        float2 _a = *(const float2*)(_p); \
        dst[0]=_a.x; dst[1]=_a.y; \
    } \
} while (0)

#define SCORE(P, pl) do { \
    P = 0.f; \
    _Pragma("unroll") \
    for (int _j = 0; _j < PL; _j++) { \
        float _v = pl[_j] + rxr[_j]; \
        _v = fmaxf(_v, 0.2f * _v); \
        P = fmaf(ratt[_j], _v, P); \
    } \
    _Pragma("unroll") \
    for (int _o = LPH / 2; _o > 0; _o >>= 1) \
        P += __shfl_xor_sync(0xffffffffu, P, _o); \
} while (0)

#define ONLINE(P, pl) do { \
    float _mn = fmaxf(m, P); \
    float _sc = __expf(m - _mn); \
    float _w  = __expf(P - _mn); \
    s = fmaf(s, _sc, _w); \
    _Pragma("unroll") \
    for (int _j = 0; _j < PL; _j++) \
        acc[_j] = fmaf(acc[_j], _sc, _w * pl[_j]); \
    m = _mn; \
} while (0)

    int i = row;
    for (; i + 2 <= end; i += 2) {
        int s0 = csrc[i], s1 = csrc[i + 1];
        float pl0[PL], pl1[PL];
        LOAD_PL(pl0, s0);
        LOAD_PL(pl1, s1);
        float p0, p1;
        SCORE(p0, pl0);
        SCORE(p1, pl1);
        ONLINE(p0, pl0);
        ONLINE(p1, pl1);
    }
    if (i < end) {
        int s0 = csrc[i];
        float pl0[PL];
        LOAD_PL(pl0, s0);
        float p0;
        SCORE(p0, pl0);
        ONLINE(p0, pl0);
    }
#undef LOAD_PL
#undef SCORE
#undef ONLINE

    float inv = 1.f / (s + 1e-16f);
    float* op = out + (size_t)nid * HC + lane * PL;
    const float* bp = bias + lane * PL;
#pragma unroll
    for (int j = 0; j < PL; j++) {
        float v = acc[j] * inv + bp[j];
        if constexpr (ELU) v = v > 0.f ? v : expm1f(v);
        op[j] = v;
    }
}

// ======================= host driver =========================================
extern "C" void kernel_launch(void* const* d_in, const int* in_sizes, int n_in,
                              void* d_out, int out_size)
{
    const float* x    = (const float*)d_in[0];
    const float* Wl1  = (const float*)d_in[1];
    const float* Wr1  = (const float*)d_in[2];
    const float* att1 = (const float*)d_in[3];
    const float* b1   = (const float*)d_in[4];
    const float* Wl2  = (const float*)d_in[5];
    const float* Wr2  = (const float*)d_in[6];
    const float* att2 = (const float*)d_in[7];
    const float* b2   = (const float*)d_in[8];
    const float* Wl3  = (const float*)d_in[9];
    const float* Wr3  = (const float*)d_in[10];
    const float* att3 = (const float*)d_in[11];
    const float* b3   = (const float*)d_in[12];
    const float* Wlin = (const float*)d_in[13];
    const float* blin = (const float*)d_in[14];
    const int*   ei   = (const int*)d_in[15];

    const int* src = ei;
    const int* dst = ei + NEDGES;

    void* tp;
    float *xlr, *h;
    uint4 *Ah, *Al, *Bh, *Bl;
    int *deg, *rowp, *pos, *csrc;
    cudaGetSymbolAddress(&tp, g_xlr);  xlr  = (float*)tp;
    cudaGetSymbolAddress(&tp, g_h);    h    = (float*)tp;
    cudaGetSymbolAddress(&tp, g_Ah);   Ah   = (uint4*)tp;
    cudaGetSymbolAddress(&tp, g_Al);   Al   = (uint4*)tp;
    cudaGetSymbolAddress(&tp, g_Bh);   Bh   = (uint4*)tp;
    cudaGetSymbolAddress(&tp, g_Bl);   Bl   = (uint4*)tp;
    cudaGetSymbolAddress(&tp, g_deg);  deg  = (int*)tp;
    cudaGetSymbolAddress(&tp, g_rowp); rowp = (int*)tp;
    cudaGetSymbolAddress(&tp, g_pos);  pos  = (int*)tp;
    cudaGetSymbolAddress(&tp, g_csrc); csrc = (int*)tp;

    // ---- CSR build (once; reused by all 3 layers) ----
    cudaMemsetAsync(deg, 0, (size_t)(NNODES + 1) * sizeof(int), 0);
    hist_kernel<<<(NEDGES + 255) / 256, 256>>>(dst, deg, NEDGES);
    scan_kernel<<<1, 1024>>>(deg, rowp, pos, NNODES, NEDGES);
    fillcsr_kernel<<<(NEDGES + 255) / 256, 256>>>(src, dst, pos, csrc, NEDGES);

    const int NB = (NNODES + 7) / 8;
    const int MTB = (NNODES + 127) / 128;   // 391 CTA rows

    // ---- Layer 1: K=128 (Kt=8) -> N2=512, ELU ----
    {
        int Kt = 8, HC = 256, N2 = 512;
        int athr = MT_PAD * Kt * 32;
        splitA_frag<<<(athr + 255) / 256, 256>>>(x, Ah, Al, NNODES, Kt);
        int bthr = (N2 / 16) * Kt * 32;
        packB_frag<<<(bthr + 255) / 256, 256>>>(Wl1, Wr1, Bh, Bl, Kt, HC);
        mma_gemm<<<dim3(N2 / 128, MTB), 256>>>(Ah, Al, Bh, Bl, xlr, NNODES, Kt, N2);
        node_agg<4, 64, true><<<NB, 256>>>(xlr, rowp, csrc, att1, b1, h, NNODES);
    }
    // ---- Layer 2: K=256 (Kt=16) -> N2=512, ELU ----
    {
        int Kt = 16, HC = 256, N2 = 512;
        int athr = MT_PAD * Kt * 32;
        splitA_frag<<<(athr + 255) / 256, 256>>>(h, Ah, Al, NNODES, Kt);
        int bthr = (N2 / 16) * Kt * 32;
        packB_frag<<<(bthr + 255) / 256, 256>>>(Wl2, Wr2, Bh, Bl, Kt, HC);
        mma_gemm<<<dim3(N2 / 128, MTB), 256>>>(Ah, Al, Bh, Bl, xlr, NNODES, Kt, N2);
        node_agg<4, 64, true><<<NB, 256>>>(xlr, rowp, csrc, att2, b2, h, NNODES);
    }
    // ---- Layer 3: K=256 (Kt=16) -> N2=128, no activation ----
    {
        int Kt = 16, HC = 64, N2 = 128;
        int athr = MT_PAD * Kt * 32;
        splitA_frag<<<(athr + 255) / 256, 256>>>(h, Ah, Al, NNODES, Kt);
        int bthr = (N2 / 16) * Kt * 32;
        packB_frag<<<(bthr + 255) / 256, 256>>>(Wl3, Wr3, Bh, Bl, Kt, HC);
        mma_gemm<<<dim3(N2 / 128, MTB), 256>>>(Ah, Al, Bh, Bl, xlr, NNODES, Kt, N2);
        node_agg<1, 64, false><<<NB, 256>>>(xlr, rowp, csrc, att3, b3, h, NNODES);
    }

    // ---- Final linear: out = h @ Wlin + blin (50000x64 @ 64x64) ----
    dim3 gf(1, (NNODES + 63) / 64);
    sgemm_bias64<<<gf, 256>>>(h, Wlin, blin, (float*)d_out, NNODES, 64, 64);
}